// round 8
// baseline (speedup 1.0000x reference)
#include <cuda_runtime.h>
#include <cuda_bf16.h>
#include <math.h>
#include <cstdint>

// Shapes: B=256, R=2048, M=65536, L=64, H=4, BH=1024
typedef unsigned long long ull;

// ---------------- device scratch ----------------
__device__ float g_rsT[2048 * 256];                 // reservoir transposed [k][b]
__device__ float g_WkT[2048 * 256];                 // Wk transposed [k][n]
__device__ float g_pk[16 * 256 * 256];              // split-K partials for keys (4 MB)
__device__ __nv_bfloat16 g_key_hi[1024 * 64];       // scaled keys, bf16 hi  [bh][l]
__device__ __nv_bfloat16 g_key_lo[1024 * 64];       // scaled keys, bf16 lo
__device__ __nv_bfloat16 g_mem_hi[65536 * 64];      // memory, bf16 hi [m][l]
__device__ __nv_bfloat16 g_mem_lo[65536 * 64];      // memory, bf16 lo
__device__ float g_sumsP[1024 * 512];               // per (row, m-tile) partial expsums
__device__ float g_invsum[1024];

// ---------------- packed fp32 helpers (k1a) ----------------
__device__ __forceinline__ ull packdup(float x) {
    ull r; asm("mov.b64 %0, {%1, %1};" : "=l"(r) : "f"(x)); return r;
}
__device__ __forceinline__ ull pack2(float x, float y) {
    ull r; asm("mov.b64 %0, {%1, %2};" : "=l"(r) : "f"(x), "f"(y)); return r;
}
__device__ __forceinline__ void fma2(ull &d, ull a, ull b) {
    asm("fma.rn.f32x2 %0, %1, %2, %0;" : "+l"(d) : "l"(a), "l"(b));
}
__device__ __forceinline__ float2 unpack2(ull v) {
    float2 f; asm("mov.b64 {%0, %1}, %2;" : "=f"(f.x), "=f"(f.y) : "l"(v)); return f;
}

// ---------------- HMMA / ldmatrix / cp.async helpers ----------------
__device__ __forceinline__ void mma_bf16(float* d, uint32_t a0, uint32_t a1,
                                         uint32_t a2, uint32_t a3,
                                         uint32_t b0, uint32_t b1) {
    asm volatile(
        "mma.sync.aligned.m16n8k16.row.col.f32.bf16.bf16.f32 "
        "{%0,%1,%2,%3}, {%4,%5,%6,%7}, {%8,%9}, {%0,%1,%2,%3};"
        : "+f"(d[0]), "+f"(d[1]), "+f"(d[2]), "+f"(d[3])
        : "r"(a0), "r"(a1), "r"(a2), "r"(a3), "r"(b0), "r"(b1));
}
__device__ __forceinline__ void ldsm_x4(uint32_t& r0, uint32_t& r1, uint32_t& r2,
                                        uint32_t& r3, uint32_t addr) {
    asm volatile("ldmatrix.sync.aligned.m8n8.x4.shared.b16 {%0,%1,%2,%3}, [%4];"
                 : "=r"(r0), "=r"(r1), "=r"(r2), "=r"(r3) : "r"(addr));
}
__device__ __forceinline__ uint32_t smem_u32(const void* p) {
    uint32_t a;
    asm("{ .reg .u64 t; cvta.to.shared.u64 t, %1; cvt.u32.u64 %0, t; }" : "=r"(a) : "l"(p));
    return a;
}
#define CP16(dst, src) \
    asm volatile("cp.async.cg.shared.global [%0], [%1], 16;" :: "r"(dst), "l"(src))
#define CP_COMMIT() asm volatile("cp.async.commit_group;" ::: "memory")
#define CP_WAIT1()  asm volatile("cp.async.wait_group 1;" ::: "memory")
#define CP_WAIT0()  asm volatile("cp.async.wait_group 0;" ::: "memory")

// ---------------- merged front kernel: mem->bf16 hi/lo + both transposes ----------------
__device__ __forceinline__ void transpose_tile(const float* __restrict__ in,
                                               float* __restrict__ out, int rows, int cols,
                                               int bx, int by, float (*t)[33]) {
    int tx = threadIdx.x & 31, ty = threadIdx.x >> 5;
    int c0 = bx * 32, r0 = by * 32;
#pragma unroll
    for (int j = 0; j < 4; j++)
        t[ty + 8 * j][tx] = in[(size_t)(r0 + ty + 8 * j) * cols + c0 + tx];
    __syncthreads();
#pragma unroll
    for (int j = 0; j < 4; j++)
        out[(size_t)(c0 + ty + 8 * j) * rows + r0 + tx] = t[tx][ty + 8 * j];
}

__global__ void front(const float* __restrict__ mem, const float* __restrict__ rs,
                      const float* __restrict__ wk) {
    __shared__ float t[32][33];
    int bid = blockIdx.x;
    if (bid < 2048) {
        size_t i = (size_t)bid * 256 + threadIdx.x;
        const float4* p = (const float4*)mem + i * 2;
        float4 a = p[0], b = p[1];
        float v[8] = {a.x, a.y, a.z, a.w, b.x, b.y, b.z, b.w};
        __align__(16) __nv_bfloat16 hh[8], ll[8];
#pragma unroll
        for (int j = 0; j < 8; j++) {
            hh[j] = __float2bfloat16_rn(v[j]);
            ll[j] = __float2bfloat16_rn(v[j] - __bfloat162float(hh[j]));
        }
        *(uint4*)&g_mem_hi[i * 8] = *(uint4*)hh;
        *(uint4*)&g_mem_lo[i * 8] = *(uint4*)ll;
    } else {
        int tb = bid - 2048;
        int which = tb >> 9, rem = tb & 511;
        int bx = rem & 63, by = rem >> 6;
        if (which == 0) transpose_tile(rs, g_rsT, 256, 2048, bx, by, t);
        else            transpose_tile(wk, g_WkT, 256, 2048, bx, by, t);
    }
}

// ---------------- k1a: split-K GEMM for key projection (16 splits of K=128) ----------------
__global__ __launch_bounds__(256, 2) void k1a_keys_gemm() {
    int n0 = blockIdx.x * 128, b0 = blockIdx.y * 128, kb = blockIdx.z * 128;
    int tid = threadIdx.x, tx = tid & 15, ty = tid >> 4;
    __shared__ float At[32][128];
    __shared__ float Bt[32][128];
    ull acc[8][4];
#pragma unroll
    for (int i = 0; i < 8; i++)
#pragma unroll
        for (int j = 0; j < 4; j++) acc[i][j] = 0ull;

    for (int kc = 0; kc < 128; kc += 32) {
#pragma unroll
        for (int it = 0; it < 4; it++) {
            int idx = tid + it * 256;
            int r = idx >> 5, c = (idx & 31) * 4;
            *(float4*)&At[r][c] = *(const float4*)&g_rsT[(size_t)(kb + kc + r) * 256 + b0 + c];
            *(float4*)&Bt[r][c] = *(const float4*)&g_WkT[(size_t)(kb + kc + r) * 256 + n0 + c];
        }
        __syncthreads();
#pragma unroll 8
        for (int k = 0; k < 32; k++) {
            float4 a0 = *(float4*)&At[k][ty * 4];
            float4 a1 = *(float4*)&At[k][64 + ty * 4];
            float4 b0v = *(float4*)&Bt[k][tx * 4];
            float4 b1v = *(float4*)&Bt[k][64 + tx * 4];
            ull bp0 = pack2(b0v.x, b0v.y), bp1 = pack2(b0v.z, b0v.w);
            ull bp2 = pack2(b1v.x, b1v.y), bp3 = pack2(b1v.z, b1v.w);
            float av[8] = {a0.x, a0.y, a0.z, a0.w, a1.x, a1.y, a1.z, a1.w};
#pragma unroll
            for (int i = 0; i < 8; i++) {
                ull ad = packdup(av[i]);
                fma2(acc[i][0], ad, bp0); fma2(acc[i][1], ad, bp1);
                fma2(acc[i][2], ad, bp2); fma2(acc[i][3], ad, bp3);
            }
        }
        __syncthreads();
    }
    int z = blockIdx.z;
#pragma unroll
    for (int i = 0; i < 8; i++) {
        int rl = (i < 4) ? (ty * 4 + i) : (64 + ty * 4 + (i - 4));
        float2 v0 = unpack2(acc[i][0]), v1 = unpack2(acc[i][1]);
        float2 v2 = unpack2(acc[i][2]), v3 = unpack2(acc[i][3]);
        size_t base = (size_t)z * 65536 + (size_t)(b0 + rl) * 256 + n0;
        *(float4*)&g_pk[base + tx * 4]      = make_float4(v0.x, v0.y, v1.x, v1.y);
        *(float4*)&g_pk[base + 64 + tx * 4] = make_float4(v2.x, v2.y, v3.x, v3.y);
    }
}

// ---------------- k1b: finalize -> scaled bf16 hi/lo keys; one block per batch b ----------------
__global__ __launch_bounds__(256) void k1b_finalize(const float* __restrict__ rs,
                                                    const float* __restrict__ Wb,
                                                    const float* __restrict__ bk,
                                                    const float* __restrict__ bb) {
    int b = blockIdx.x;
    int n = threadIdx.x;              // 256 threads = 4 heads x 64 lanes
    int h = n >> 6, l = n & 63;

    float key = bk[n];
#pragma unroll
    for (int s = 0; s < 16; s++) key += g_pk[(size_t)s * 65536 + b * 256 + n];

    float bp = 0.f;
#pragma unroll 8
    for (int i = 0; i < 32; i++) {
        int idx = l + 64 * i;
        bp += rs[b * 2048 + idx] * Wb[h * 2048 + idx];
    }

    __shared__ float s1[256], s2[256];
    s1[n] = key * key; s2[n] = bp;
    __syncthreads();
    for (int o = 32; o > 0; o >>= 1) {
        if (l < o) { s1[n] += s1[n + o]; s2[n] += s2[n + o]; }
        __syncthreads();
    }
    float beta = s2[h * 64] + bb[h];
    beta = beta > 0.f ? beta : 0.f;
    float sk = key * (beta * rsqrtf(s1[h * 64]));
    __nv_bfloat16 hi = __float2bfloat16_rn(sk);
    __nv_bfloat16 lo = __float2bfloat16_rn(sk - __bfloat162float(hi));
    int bh = b * 4 + h;
    g_key_hi[bh * 64 + l] = hi;
    g_key_lo[bh * 64 + l] = lo;
}

// ---------------- k2: persistent HMMA GEMM, cp.async double-buffered B ----------------
// Each CTA: fixed bh-block (128 rows), sweeps 8 m-tiles of 128.
// PASS 0: exp row-sum partials.  PASS 1: write exp(d) * invsum to out.
static constexpr int ROW_B = 144;                       // smem row stride in bytes
static constexpr int ARR_B = 128 * ROW_B;               // 18432 per array
static constexpr int SM_A_HI = 0;
static constexpr int SM_A_LO = ARR_B;                   // 18432
static constexpr int SM_B0   = 2 * ARR_B;               // 36864 (buf stride 2*ARR_B)
static constexpr int BUF_S   = 2 * ARR_B;               // hi at +0, lo at +ARR_B
static constexpr int SM_PS   = SM_B0 + 2 * BUF_S;       // 110592
static constexpr int SMEM_K2 = SM_PS + 128 * 4 * 4;     // 112640
static constexpr int TILES   = 8;

__device__ __forceinline__ void fill_B(uint32_t sb, int buf, int m0, int tid) {
#pragma unroll
    for (int i = 0; i < 8; i++) {
        int it = tid + i * 256;                 // 2048 chunks (2 arrays x 128 rows x 8)
        int arr = it >> 10, rem = it & 1023;
        int r = rem >> 3, c16 = rem & 7;
        const __nv_bfloat16* src =
            (arr ? g_mem_lo : g_mem_hi) + (size_t)(m0 + r) * 64 + c16 * 8;
        uint32_t dst = sb + SM_B0 + buf * BUF_S + arr * ARR_B + r * ROW_B + c16 * 16;
        CP16(dst, src);
    }
}

template <int PASS>
__global__ __launch_bounds__(256, 2) void k2_mma(float* __restrict__ out) {
    extern __shared__ char smem[];
    uint32_t sb = smem_u32(smem);
    int tid = threadIdx.x, wid = tid >> 5, lid = tid & 31;
    int wr = wid >> 2, wc = wid & 3;          // warp grid 2x4
    int g = lid >> 2, c = lid & 3;            // groupID / thread-in-group
    int bt = blockIdx.x, mg = blockIdx.y;
    int bh0 = bt * 128;
    int mt0 = mg * TILES;

    // ---- prologue: A fill (cp.async) + B tile0 fill, one commit group
#pragma unroll
    for (int i = 0; i < 8; i++) {
        int it = tid + i * 256;                 // 2048 chunks (2 arrays x 128 rows x 8)
        int arr = it >> 10, rem = it & 1023;
        int r = rem >> 3, c16 = rem & 7;
        const __nv_bfloat16* src =
            (arr ? g_key_lo : g_key_hi) + (size_t)(bh0 + r) * 64 + c16 * 8;
        uint32_t dst = sb + (arr ? SM_A_LO : SM_A_HI) + r * ROW_B + c16 * 16;
        CP16(dst, src);
    }
    fill_B(sb, 0, mt0 * 128, tid);
    CP_COMMIT();

    // ldmatrix lane address offsets (relative to array base)
    int rw = lid & 7;
    uint32_t aOff = (uint32_t)((wr * 64 + rw + ((lid >> 3) & 1) * 8) * ROW_B
                               + ((lid >> 4) & 1) * 16);
    uint32_t bOff = (uint32_t)((wc * 32 + rw + ((lid >> 4) & 1) * 8) * ROW_B
                               + ((lid >> 3) & 1) * 16);

    // pass-1 per-row invsum (row set fixed across tiles)
    float inv0[4], inv1[4];
    if (PASS == 1) {
#pragma unroll
        for (int mi = 0; mi < 4; mi++) {
            int r0 = bh0 + wr * 64 + mi * 16 + g;
            inv0[mi] = g_invsum[r0];
            inv1[mi] = g_invsum[r0 + 8];
        }
    }

    for (int t = 0; t < TILES; t++) {
        if (t < TILES - 1) {
            fill_B(sb, (t + 1) & 1, (mt0 + t + 1) * 128, tid);
            CP_COMMIT();
            CP_WAIT1();
        } else {
            CP_WAIT0();
        }
        __syncthreads();

        int mt = mt0 + t;
        int m0 = mt * 128;
        uint32_t bBase = sb + SM_B0 + (t & 1) * BUF_S;

        float acc[4][4][4];
#pragma unroll
        for (int mi = 0; mi < 4; mi++)
#pragma unroll
            for (int ni = 0; ni < 4; ni++)
#pragma unroll
                for (int q = 0; q < 4; q++) acc[mi][ni][q] = 0.f;

#pragma unroll
        for (int kk = 0; kk < 4; kk++) {
            uint32_t ah[4][4], al[4][4];
#pragma unroll
            for (int mi = 0; mi < 4; mi++) {
                uint32_t ao = sb + aOff + mi * 16 * ROW_B + kk * 32;
                ldsm_x4(ah[mi][0], ah[mi][1], ah[mi][2], ah[mi][3], ao + SM_A_HI);
                ldsm_x4(al[mi][0], al[mi][1], al[mi][2], al[mi][3], ao + SM_A_LO);
            }
#pragma unroll
            for (int p = 0; p < 2; p++) {
                uint32_t bh_[4], bl_[4];
                uint32_t bo = bBase + bOff + p * 16 * ROW_B + kk * 32;
                ldsm_x4(bh_[0], bh_[1], bh_[2], bh_[3], bo);
                ldsm_x4(bl_[0], bl_[1], bl_[2], bl_[3], bo + ARR_B);
#pragma unroll
                for (int mi = 0; mi < 4; mi++)
#pragma unroll
                    for (int q = 0; q < 2; q++) {
                        int ni = p * 2 + q;
                        mma_bf16(acc[mi][ni], ah[mi][0], ah[mi][1], ah[mi][2], ah[mi][3],
                                 bh_[q * 2], bh_[q * 2 + 1]);
                        mma_bf16(acc[mi][ni], ah[mi][0], ah[mi][1], ah[mi][2], ah[mi][3],
                                 bl_[q * 2], bl_[q * 2 + 1]);
                        mma_bf16(acc[mi][ni], al[mi][0], al[mi][1], al[mi][2], al[mi][3],
                                 bh_[q * 2], bh_[q * 2 + 1]);
                    }
            }
        }

        if (PASS == 0) {
            float* ps = (float*)(smem + SM_PS);     // ps[row 128][wc 4]
#pragma unroll
            for (int mi = 0; mi < 4; mi++) {
                float s0 = 0.f, s1 = 0.f;
#pragma unroll
                for (int ni = 0; ni < 4; ni++) {
                    s0 += __expf(acc[mi][ni][0]) + __expf(acc[mi][ni][1]);
                    s1 += __expf(acc[mi][ni][2]) + __expf(acc[mi][ni][3]);
                }
                s0 += __shfl_xor_sync(0xffffffffu, s0, 1);
                s0 += __shfl_xor_sync(0xffffffffu, s0, 2);
                s1 += __shfl_xor_sync(0xffffffffu, s1, 1);
                s1 += __shfl_xor_sync(0xffffffffu, s1, 2);
                if (c == 0) {
                    int r0 = wr * 64 + mi * 16 + g;
                    ps[r0 * 4 + wc] = s0;
                    ps[(r0 + 8) * 4 + wc] = s1;
                }
            }
            __syncthreads();
            if (tid < 128) {
                float s = (ps[tid * 4 + 0] + ps[tid * 4 + 1]) +
                          (ps[tid * 4 + 2] + ps[tid * 4 + 3]);
                g_sumsP[(size_t)(bh0 + tid) * 512 + mt] = s;
            }
            __syncthreads();
        } else {
#pragma unroll
            for (int mi = 0; mi < 4; mi++) {
                int r0 = bh0 + wr * 64 + mi * 16 + g;
                size_t ob0 = (size_t)r0 * 65536 + m0 + wc * 32;
                size_t ob1 = (size_t)(r0 + 8) * 65536 + m0 + wc * 32;
#pragma unroll
                for (int ni = 0; ni < 4; ni++) {
                    int col = ni * 8 + 2 * c;
                    float2 v0 = make_float2(__expf(acc[mi][ni][0]) * inv0[mi],
                                            __expf(acc[mi][ni][1]) * inv0[mi]);
                    float2 v1 = make_float2(__expf(acc[mi][ni][2]) * inv1[mi],
                                            __expf(acc[mi][ni][3]) * inv1[mi]);
                    *(float2*)&out[ob0 + col] = v0;
                    *(float2*)&out[ob1 + col] = v1;
                }
            }
            __syncthreads();
        }
    }
}

// ---------------- k3: reduce partial sums -> 1/rowsum ----------------
__global__ void k3_reduce() {
    int bh = blockIdx.x, t = threadIdx.x;   // 128 threads
    float s = 0.f;
#pragma unroll
    for (int j = 0; j < 4; j++) s += g_sumsP[(size_t)bh * 512 + t + 128 * j];
    __shared__ float red[128];
    red[t] = s;
    __syncthreads();
    for (int o = 64; o > 0; o >>= 1) {
        if (t < o) red[t] += red[t + o];
        __syncthreads();
    }
    if (t == 0) g_invsum[bh] = 1.0f / red[0];
}

// ---------------- launch ----------------
extern "C" void kernel_launch(void* const* d_in, const int* in_sizes, int n_in,
                              void* d_out, int out_size) {
    const float* rs  = (const float*)d_in[0];   // [256, 2048]
    const float* mem = (const float*)d_in[1];   // [1, 65536, 64]
    const float* Wk  = (const float*)d_in[2];   // [256, 2048]
    const float* bk  = (const float*)d_in[3];   // [256]
    const float* Wb  = (const float*)d_in[4];   // [4, 2048]
    const float* bb  = (const float*)d_in[5];   // [4]
    float* out = (float*)d_out;                 // [256, 4, 65536]
    (void)in_sizes; (void)n_in; (void)out_size;

    cudaFuncSetAttribute(k2_mma<0>, cudaFuncAttributeMaxDynamicSharedMemorySize, SMEM_K2);
    cudaFuncSetAttribute(k2_mma<1>, cudaFuncAttributeMaxDynamicSharedMemorySize, SMEM_K2);

    front<<<3072, 256>>>(mem, rs, Wk);
    k1a_keys_gemm<<<dim3(2, 2, 16), 256>>>();
    k1b_finalize<<<256, 256>>>(rs, Wb, bk, bb);

    k2_mma<0><<<dim3(8, 64), 256, SMEM_K2>>>(nullptr);
    k3_reduce<<<1024, 128>>>();
    k2_mma<1><<<dim3(8, 64), 256, SMEM_K2>>>(out);
}

// round 9
// speedup vs baseline: 1.0990x; 1.0990x over previous
#include <cuda_runtime.h>
#include <cuda_bf16.h>
#include <math.h>
#include <cstdint>

// Shapes: B=256, R=2048, M=65536, L=64, H=4, BH=1024
typedef unsigned long long ull;

// ---------------- device scratch ----------------
__device__ float g_rsT[2048 * 256];                 // reservoir transposed [k][b]
__device__ float g_WkT[2048 * 256];                 // Wk transposed [k][n]
__device__ float g_pk[16 * 256 * 256];              // split-K partials for keys (4 MB)
__device__ __nv_bfloat16 g_key_hi[1024 * 64];       // scaled keys, bf16 hi  [bh][l]
__device__ __nv_bfloat16 g_key_lo[1024 * 64];       // scaled keys, bf16 lo
__device__ __nv_bfloat16 g_mem_hi[65536 * 64];      // memory, bf16 hi [m][l]
__device__ __nv_bfloat16 g_mem_lo[65536 * 64];      // memory, bf16 lo
__device__ float g_sumsP[1024 * 2048];              // per (row, mt*4+wc) partial expsums (8 MB)
__device__ float g_invsum[1024];

// ---------------- packed fp32 helpers (k1a) ----------------
__device__ __forceinline__ ull packdup(float x) {
    ull r; asm("mov.b64 %0, {%1, %1};" : "=l"(r) : "f"(x)); return r;
}
__device__ __forceinline__ ull pack2(float x, float y) {
    ull r; asm("mov.b64 %0, {%1, %2};" : "=l"(r) : "f"(x), "f"(y)); return r;
}
__device__ __forceinline__ void fma2(ull &d, ull a, ull b) {
    asm("fma.rn.f32x2 %0, %1, %2, %0;" : "+l"(d) : "l"(a), "l"(b));
}
__device__ __forceinline__ float2 unpack2(ull v) {
    float2 f; asm("mov.b64 {%0, %1}, %2;" : "=f"(f.x), "=f"(f.y) : "l"(v)); return f;
}

// ---------------- HMMA / ldmatrix / cp.async helpers ----------------
__device__ __forceinline__ void mma_bf16(float* d, uint32_t a0, uint32_t a1,
                                         uint32_t a2, uint32_t a3,
                                         uint32_t b0, uint32_t b1) {
    asm volatile(
        "mma.sync.aligned.m16n8k16.row.col.f32.bf16.bf16.f32 "
        "{%0,%1,%2,%3}, {%4,%5,%6,%7}, {%8,%9}, {%0,%1,%2,%3};"
        : "+f"(d[0]), "+f"(d[1]), "+f"(d[2]), "+f"(d[3])
        : "r"(a0), "r"(a1), "r"(a2), "r"(a3), "r"(b0), "r"(b1));
}
__device__ __forceinline__ void ldsm_x4(uint32_t& r0, uint32_t& r1, uint32_t& r2,
                                        uint32_t& r3, uint32_t addr) {
    asm volatile("ldmatrix.sync.aligned.m8n8.x4.shared.b16 {%0,%1,%2,%3}, [%4];"
                 : "=r"(r0), "=r"(r1), "=r"(r2), "=r"(r3) : "r"(addr));
}
__device__ __forceinline__ uint32_t smem_u32(const void* p) {
    uint32_t a;
    asm("{ .reg .u64 t; cvta.to.shared.u64 t, %1; cvt.u32.u64 %0, t; }" : "=r"(a) : "l"(p));
    return a;
}
#define CP16(dst, src) \
    asm volatile("cp.async.cg.shared.global [%0], [%1], 16;" :: "r"(dst), "l"(src))
#define CP_COMMIT() asm volatile("cp.async.commit_group;" ::: "memory")
#define CP_WAIT1()  asm volatile("cp.async.wait_group 1;" ::: "memory")
#define CP_WAIT0()  asm volatile("cp.async.wait_group 0;" ::: "memory")

// ---------------- merged front kernel: mem->bf16 hi/lo + both transposes ----------------
__device__ __forceinline__ void transpose_tile(const float* __restrict__ in,
                                               float* __restrict__ out, int rows, int cols,
                                               int bx, int by, float (*t)[33]) {
    int tx = threadIdx.x & 31, ty = threadIdx.x >> 5;
    int c0 = bx * 32, r0 = by * 32;
#pragma unroll
    for (int j = 0; j < 4; j++)
        t[ty + 8 * j][tx] = in[(size_t)(r0 + ty + 8 * j) * cols + c0 + tx];
    __syncthreads();
#pragma unroll
    for (int j = 0; j < 4; j++)
        out[(size_t)(c0 + ty + 8 * j) * rows + r0 + tx] = t[tx][ty + 8 * j];
}

__global__ void front(const float* __restrict__ mem, const float* __restrict__ rs,
                      const float* __restrict__ wk) {
    __shared__ float t[32][33];
    int bid = blockIdx.x;
    if (bid < 2048) {
        size_t i = (size_t)bid * 256 + threadIdx.x;
        const float4* p = (const float4*)mem + i * 2;
        float4 a = p[0], b = p[1];
        float v[8] = {a.x, a.y, a.z, a.w, b.x, b.y, b.z, b.w};
        __align__(16) __nv_bfloat16 hh[8], ll[8];
#pragma unroll
        for (int j = 0; j < 8; j++) {
            hh[j] = __float2bfloat16_rn(v[j]);
            ll[j] = __float2bfloat16_rn(v[j] - __bfloat162float(hh[j]));
        }
        *(uint4*)&g_mem_hi[i * 8] = *(uint4*)hh;
        *(uint4*)&g_mem_lo[i * 8] = *(uint4*)ll;
    } else {
        int tb = bid - 2048;
        int which = tb >> 9, rem = tb & 511;
        int bx = rem & 63, by = rem >> 6;
        if (which == 0) transpose_tile(rs, g_rsT, 256, 2048, bx, by, t);
        else            transpose_tile(wk, g_WkT, 256, 2048, bx, by, t);
    }
}

// ---------------- k1a: split-K GEMM for key projection (16 splits of K=128) ----------------
__global__ __launch_bounds__(256, 2) void k1a_keys_gemm() {
    int n0 = blockIdx.x * 128, b0 = blockIdx.y * 128, kb = blockIdx.z * 128;
    int tid = threadIdx.x, tx = tid & 15, ty = tid >> 4;
    __shared__ float At[32][128];
    __shared__ float Bt[32][128];
    ull acc[8][4];
#pragma unroll
    for (int i = 0; i < 8; i++)
#pragma unroll
        for (int j = 0; j < 4; j++) acc[i][j] = 0ull;

    for (int kc = 0; kc < 128; kc += 32) {
#pragma unroll
        for (int it = 0; it < 4; it++) {
            int idx = tid + it * 256;
            int r = idx >> 5, c = (idx & 31) * 4;
            *(float4*)&At[r][c] = *(const float4*)&g_rsT[(size_t)(kb + kc + r) * 256 + b0 + c];
            *(float4*)&Bt[r][c] = *(const float4*)&g_WkT[(size_t)(kb + kc + r) * 256 + n0 + c];
        }
        __syncthreads();
#pragma unroll 8
        for (int k = 0; k < 32; k++) {
            float4 a0 = *(float4*)&At[k][ty * 4];
            float4 a1 = *(float4*)&At[k][64 + ty * 4];
            float4 b0v = *(float4*)&Bt[k][tx * 4];
            float4 b1v = *(float4*)&Bt[k][64 + tx * 4];
            ull bp0 = pack2(b0v.x, b0v.y), bp1 = pack2(b0v.z, b0v.w);
            ull bp2 = pack2(b1v.x, b1v.y), bp3 = pack2(b1v.z, b1v.w);
            float av[8] = {a0.x, a0.y, a0.z, a0.w, a1.x, a1.y, a1.z, a1.w};
#pragma unroll
            for (int i = 0; i < 8; i++) {
                ull ad = packdup(av[i]);
                fma2(acc[i][0], ad, bp0); fma2(acc[i][1], ad, bp1);
                fma2(acc[i][2], ad, bp2); fma2(acc[i][3], ad, bp3);
            }
        }
        __syncthreads();
    }
    int z = blockIdx.z;
#pragma unroll
    for (int i = 0; i < 8; i++) {
        int rl = (i < 4) ? (ty * 4 + i) : (64 + ty * 4 + (i - 4));
        float2 v0 = unpack2(acc[i][0]), v1 = unpack2(acc[i][1]);
        float2 v2 = unpack2(acc[i][2]), v3 = unpack2(acc[i][3]);
        size_t base = (size_t)z * 65536 + (size_t)(b0 + rl) * 256 + n0;
        *(float4*)&g_pk[base + tx * 4]      = make_float4(v0.x, v0.y, v1.x, v1.y);
        *(float4*)&g_pk[base + 64 + tx * 4] = make_float4(v2.x, v2.y, v3.x, v3.y);
    }
}

// ---------------- k1b: finalize -> scaled bf16 hi/lo keys; one block per batch b ----------------
__global__ __launch_bounds__(256) void k1b_finalize(const float* __restrict__ rs,
                                                    const float* __restrict__ Wb,
                                                    const float* __restrict__ bk,
                                                    const float* __restrict__ bb) {
    int b = blockIdx.x;
    int n = threadIdx.x;              // 256 threads = 4 heads x 64 lanes
    int h = n >> 6, l = n & 63;

    float key = bk[n];
#pragma unroll
    for (int s = 0; s < 16; s++) key += g_pk[(size_t)s * 65536 + b * 256 + n];

    float bp = 0.f;
#pragma unroll 8
    for (int i = 0; i < 32; i++) {
        int idx = l + 64 * i;
        bp += rs[b * 2048 + idx] * Wb[h * 2048 + idx];
    }

    __shared__ float s1[256], s2[256];
    s1[n] = key * key; s2[n] = bp;
    __syncthreads();
    for (int o = 32; o > 0; o >>= 1) {
        if (l < o) { s1[n] += s1[n + o]; s2[n] += s2[n + o]; }
        __syncthreads();
    }
    float beta = s2[h * 64] + bb[h];
    beta = beta > 0.f ? beta : 0.f;
    float sk = key * (beta * rsqrtf(s1[h * 64]));
    __nv_bfloat16 hi = __float2bfloat16_rn(sk);
    __nv_bfloat16 lo = __float2bfloat16_rn(sk - __bfloat162float(hi));
    int bh = b * 4 + h;
    g_key_hi[bh * 64 + l] = hi;
    g_key_lo[bh * 64 + l] = lo;
}

// ---------------- k2: persistent one-wave HMMA GEMM, cp.async double-buffered B ----------------
// Grid 8 bt x 37 mg = 296 CTAs (one full wave at 2 CTAs/SM).
// Each CTA: fixed bh-block (128 rows), m-tiles mt = mg, mg+37, ... (< 512).
static constexpr int ROW_B = 144;                       // smem row stride in bytes
static constexpr int ARR_B = 128 * ROW_B;               // 18432 per array
static constexpr int SM_A_HI = 0;
static constexpr int SM_A_LO = ARR_B;                   // 18432
static constexpr int SM_B0   = 2 * ARR_B;               // 36864 (buf stride 2*ARR_B)
static constexpr int BUF_S   = 2 * ARR_B;               // hi at +0, lo at +ARR_B
static constexpr int SMEM_K2 = SM_B0 + 2 * BUF_S;       // 110592
static constexpr int MT_STRIDE = 37;
static constexpr int MT_TOT  = 512;

__device__ __forceinline__ void fill_B(uint32_t sb, int buf, int m0, int tid) {
#pragma unroll
    for (int i = 0; i < 8; i++) {
        int it = tid + i * 256;                 // 2048 chunks (2 arrays x 128 rows x 8)
        int arr = it >> 10, rem = it & 1023;
        int r = rem >> 3, c16 = rem & 7;
        const __nv_bfloat16* src =
            (arr ? g_mem_lo : g_mem_hi) + (size_t)(m0 + r) * 64 + c16 * 8;
        uint32_t dst = sb + SM_B0 + buf * BUF_S + arr * ARR_B + r * ROW_B + c16 * 16;
        CP16(dst, src);
    }
}

template <int PASS>
__global__ __launch_bounds__(256, 2) void k2_mma(float* __restrict__ out) {
    extern __shared__ char smem[];
    uint32_t sb = smem_u32(smem);
    int tid = threadIdx.x, wid = tid >> 5, lid = tid & 31;
    int wr = wid >> 2, wc = wid & 3;          // warp grid 2x4
    int g = lid >> 2, c = lid & 3;            // groupID / thread-in-group
    int bt = blockIdx.x, mg = blockIdx.y;
    int bh0 = bt * 128;

    // ---- prologue: A fill (cp.async) + B tile0 fill, one commit group
#pragma unroll
    for (int i = 0; i < 8; i++) {
        int it = tid + i * 256;
        int arr = it >> 10, rem = it & 1023;
        int r = rem >> 3, c16 = rem & 7;
        const __nv_bfloat16* src =
            (arr ? g_key_lo : g_key_hi) + (size_t)(bh0 + r) * 64 + c16 * 8;
        uint32_t dst = sb + (arr ? SM_A_LO : SM_A_HI) + r * ROW_B + c16 * 16;
        CP16(dst, src);
    }
    fill_B(sb, 0, mg * 128, tid);
    CP_COMMIT();

    // ldmatrix lane address offsets
    int rw = lid & 7;
    uint32_t aOff = (uint32_t)((wr * 64 + rw + ((lid >> 3) & 1) * 8) * ROW_B
                               + ((lid >> 4) & 1) * 16);
    uint32_t bOff = (uint32_t)((wc * 32 + rw + ((lid >> 4) & 1) * 8) * ROW_B
                               + ((lid >> 3) & 1) * 16);

    float inv0[4], inv1[4];
    if (PASS == 1) {
#pragma unroll
        for (int mi = 0; mi < 4; mi++) {
            int r0 = bh0 + wr * 64 + mi * 16 + g;
            inv0[mi] = g_invsum[r0];
            inv1[mi] = g_invsum[r0 + 8];
        }
    }

    int mt = mg, buf = 0;
    while (true) {
        int next = mt + MT_STRIDE;
        if (next < MT_TOT) {
            fill_B(sb, buf ^ 1, next * 128, tid);
            CP_COMMIT();
            CP_WAIT1();
        } else {
            CP_WAIT0();
        }
        __syncthreads();

        int m0 = mt * 128;
        uint32_t bBase = sb + SM_B0 + buf * BUF_S;

        float acc[4][4][4];
#pragma unroll
        for (int mi = 0; mi < 4; mi++)
#pragma unroll
            for (int ni = 0; ni < 4; ni++)
#pragma unroll
                for (int q = 0; q < 4; q++) acc[mi][ni][q] = 0.f;

#pragma unroll
        for (int kk = 0; kk < 4; kk++) {
            uint32_t ah[4][4], al[4][4];
#pragma unroll
            for (int mi = 0; mi < 4; mi++) {
                uint32_t ao = sb + aOff + mi * 16 * ROW_B + kk * 32;
                ldsm_x4(ah[mi][0], ah[mi][1], ah[mi][2], ah[mi][3], ao + SM_A_HI);
                ldsm_x4(al[mi][0], al[mi][1], al[mi][2], al[mi][3], ao + SM_A_LO);
            }
#pragma unroll
            for (int p = 0; p < 2; p++) {
                uint32_t bh_[4], bl_[4];
                uint32_t bo = bBase + bOff + p * 16 * ROW_B + kk * 32;
                ldsm_x4(bh_[0], bh_[1], bh_[2], bh_[3], bo);
                ldsm_x4(bl_[0], bl_[1], bl_[2], bl_[3], bo + ARR_B);
#pragma unroll
                for (int mi = 0; mi < 4; mi++)
#pragma unroll
                    for (int q = 0; q < 2; q++) {
                        int ni = p * 2 + q;
                        mma_bf16(acc[mi][ni], ah[mi][0], ah[mi][1], ah[mi][2], ah[mi][3],
                                 bh_[q * 2], bh_[q * 2 + 1]);
                        mma_bf16(acc[mi][ni], ah[mi][0], ah[mi][1], ah[mi][2], ah[mi][3],
                                 bl_[q * 2], bl_[q * 2 + 1]);
                        mma_bf16(acc[mi][ni], al[mi][0], al[mi][1], al[mi][2], al[mi][3],
                                 bh_[q * 2], bh_[q * 2 + 1]);
                    }
            }
        }

        if (PASS == 0) {
            // per-warp-column partial expsums, direct STG (no smem staging)
#pragma unroll
            for (int mi = 0; mi < 4; mi++) {
                float s0 = 0.f, s1 = 0.f;
#pragma unroll
                for (int ni = 0; ni < 4; ni++) {
                    s0 += __expf(acc[mi][ni][0]) + __expf(acc[mi][ni][1]);
                    s1 += __expf(acc[mi][ni][2]) + __expf(acc[mi][ni][3]);
                }
                s0 += __shfl_xor_sync(0xffffffffu, s0, 1);
                s0 += __shfl_xor_sync(0xffffffffu, s0, 2);
                s1 += __shfl_xor_sync(0xffffffffu, s1, 1);
                s1 += __shfl_xor_sync(0xffffffffu, s1, 2);
                if (c == 0) {
                    int r0 = bh0 + wr * 64 + mi * 16 + g;
                    g_sumsP[(size_t)r0 * 2048 + mt * 4 + wc] = s0;
                    g_sumsP[(size_t)(r0 + 8) * 2048 + mt * 4 + wc] = s1;
                }
            }
        } else {
#pragma unroll
            for (int mi = 0; mi < 4; mi++) {
                int r0 = bh0 + wr * 64 + mi * 16 + g;
                size_t ob0 = (size_t)r0 * 65536 + m0 + wc * 32;
                size_t ob1 = (size_t)(r0 + 8) * 65536 + m0 + wc * 32;
#pragma unroll
                for (int ni = 0; ni < 4; ni++) {
                    int col = ni * 8 + 2 * c;
                    float2 v0 = make_float2(__expf(acc[mi][ni][0]) * inv0[mi],
                                            __expf(acc[mi][ni][1]) * inv0[mi]);
                    float2 v1 = make_float2(__expf(acc[mi][ni][2]) * inv1[mi],
                                            __expf(acc[mi][ni][3]) * inv1[mi]);
                    *(float2*)&out[ob0 + col] = v0;
                    *(float2*)&out[ob1 + col] = v1;
                }
            }
        }

        __syncthreads();                      // guard B-buffer reuse by next fill
        if (next >= MT_TOT) break;
        mt = next; buf ^= 1;
    }
}

// ---------------- k3: reduce partial sums -> 1/rowsum ----------------
__global__ __launch_bounds__(256) void k3_reduce() {
    int bh = blockIdx.x, t = threadIdx.x;   // 256 threads
    float s = 0.f;
#pragma unroll
    for (int j = 0; j < 8; j++) s += g_sumsP[(size_t)bh * 2048 + t + 256 * j];
    __shared__ float red[256];
    red[t] = s;
    __syncthreads();
    for (int o = 128; o > 0; o >>= 1) {
        if (t < o) red[t] += red[t + o];
        __syncthreads();
    }
    if (t == 0) g_invsum[bh] = 1.0f / red[0];
}

// ---------------- launch ----------------
extern "C" void kernel_launch(void* const* d_in, const int* in_sizes, int n_in,
                              void* d_out, int out_size) {
    const float* rs  = (const float*)d_in[0];   // [256, 2048]
    const float* mem = (const float*)d_in[1];   // [1, 65536, 64]
    const float* Wk  = (const float*)d_in[2];   // [256, 2048]
    const float* bk  = (const float*)d_in[3];   // [256]
    const float* Wb  = (const float*)d_in[4];   // [4, 2048]
    const float* bb  = (const float*)d_in[5];   // [4]
    float* out = (float*)d_out;                 // [256, 4, 65536]
    (void)in_sizes; (void)n_in; (void)out_size;

    cudaFuncSetAttribute(k2_mma<0>, cudaFuncAttributeMaxDynamicSharedMemorySize, SMEM_K2);
    cudaFuncSetAttribute(k2_mma<1>, cudaFuncAttributeMaxDynamicSharedMemorySize, SMEM_K2);

    front<<<3072, 256>>>(mem, rs, Wk);
    k1a_keys_gemm<<<dim3(2, 2, 16), 256>>>();
    k1b_finalize<<<256, 256>>>(rs, Wb, bk, bb);

    k2_mma<0><<<dim3(8, 37), 256, SMEM_K2>>>(nullptr);
    k3_reduce<<<1024, 256>>>();
    k2_mma<1><<<dim3(8, 37), 256, SMEM_K2>>>(out);
}